// round 13
// baseline (speedup 1.0000x reference)
#include <cuda_runtime.h>

#define T_STEPS 512
#define BATCH   64
#define IDIM    128
#define HDIM    512
#define ZDIM    32
#define ALPHA 0.2f
#define ONEMA 0.8f

typedef unsigned long long ull;

// ---------------- device scratch (static globals; no runtime allocation) ----
__device__ float g_xin [(size_t)T_STEPS * HDIM * BATCH];        // (t, g, b)
__device__ float g_rbuf[(size_t)(T_STEPS + 1) * HDIM * BATCH];  // (t, h, b)
__device__ float g_xz  [(size_t)T_STEPS * BATCH * ZDIM];        // (t, b, z)
__device__ float g_sbuf[(size_t)T_STEPS * BATCH * 2];           // (t, b, k): s-0.5

// ---------------- helpers ---------------------------------------------------
__device__ __forceinline__ unsigned smem_u32(const void* p) {
    return (unsigned)__cvta_generic_to_shared(p);
}
// packed fp32x2 math (sm_100+)
__device__ __forceinline__ ull ffma2(ull a, ull b, ull c) {
    ull d; asm("fma.rn.f32x2 %0,%1,%2,%3;" : "=l"(d) : "l"(a), "l"(b), "l"(c)); return d;
}
__device__ __forceinline__ ull fmul2(ull a, ull b) {
    ull d; asm("mul.rn.f32x2 %0,%1,%2;" : "=l"(d) : "l"(a), "l"(b)); return d;
}
__device__ __forceinline__ ull fadd2(ull a, ull b) {
    ull d; asm("add.rn.f32x2 %0,%1,%2;" : "=l"(d) : "l"(a), "l"(b)); return d;
}
__device__ __forceinline__ ull dup2(float x) {
    ull d; asm("mov.b64 %0,{%1,%1};" : "=l"(d) : "f"(x)); return d;
}
// distributed shared memory
__device__ __forceinline__ unsigned cluster_rank() {
    unsigned r; asm("mov.u32 %0, %%cluster_ctarank;" : "=r"(r)); return r;
}
__device__ __forceinline__ unsigned mapa_u32(unsigned local_addr, unsigned rank) {
    unsigned r;
    asm("mapa.shared::cluster.u32 %0, %1, %2;" : "=r"(r) : "r"(local_addr), "r"(rank));
    return r;
}
__device__ __forceinline__ void stsc32(unsigned a, float v) {
    asm volatile("st.shared::cluster.f32 [%0], %1;" :: "r"(a), "f"(v) : "memory");
}
__device__ __forceinline__ void cluster_sync() {
    asm volatile("barrier.cluster.arrive.aligned;" ::: "memory");
    asm volatile("barrier.cluster.wait.aligned;" ::: "memory");
}

// ---------------- k_xin: xin[t,g,b] = sum_i x[b,t,i]*W_in[g,i] + b_rec[g] ----
__global__ void __launch_bounds__(128, 1) k_xin(const float* __restrict__ x,
                                                const float* __restrict__ win,
                                                const float* __restrict__ brec) {
    extern __shared__ float sm[];
    float* x_s = sm;         // [i][b]
    float* w_s = sm + 8192;  // [i][gl]
    const int tid = threadIdx.x;
    const int t   = blockIdx.x;
    const int g0  = blockIdx.y * 64;

    for (int idx = tid; idx < 8192; idx += 128) {
        int b = idx >> 7, i = idx & 127;
        x_s[i * 64 + b] = x[(size_t)b * (T_STEPS * IDIM) + t * IDIM + i];
    }
    for (int idx = tid; idx < 8192; idx += 128) {
        int gl = idx >> 7, i = idx & 127;
        w_s[i * 64 + gl] = win[(g0 + gl) * IDIM + i];
    }
    __syncthreads();

    const int gt = tid >> 3;
    const int bt = tid & 7;
    ull acc[4][4];
#pragma unroll
    for (int a = 0; a < 4; ++a)
#pragma unroll
        for (int j = 0; j < 4; ++j) acc[a][j] = 0ULL;

    const float4* wp = (const float4*)w_s + gt;
    const ull* xp = (const ull*)x_s + bt * 4;
#pragma unroll 4
    for (int i = 0; i < 128; ++i) {
        float4 wv = wp[i * 16];
        ull x0 = xp[i * 32], x1 = xp[i * 32 + 1], x2 = xp[i * 32 + 2], x3 = xp[i * 32 + 3];
        ull w0 = dup2(wv.x), w1 = dup2(wv.y), w2 = dup2(wv.z), w3 = dup2(wv.w);
        acc[0][0] = ffma2(w0, x0, acc[0][0]); acc[0][1] = ffma2(w0, x1, acc[0][1]);
        acc[0][2] = ffma2(w0, x2, acc[0][2]); acc[0][3] = ffma2(w0, x3, acc[0][3]);
        acc[1][0] = ffma2(w1, x0, acc[1][0]); acc[1][1] = ffma2(w1, x1, acc[1][1]);
        acc[1][2] = ffma2(w1, x2, acc[1][2]); acc[1][3] = ffma2(w1, x3, acc[1][3]);
        acc[2][0] = ffma2(w2, x0, acc[2][0]); acc[2][1] = ffma2(w2, x1, acc[2][1]);
        acc[2][2] = ffma2(w2, x2, acc[2][2]); acc[2][3] = ffma2(w2, x3, acc[2][3]);
        acc[3][0] = ffma2(w3, x0, acc[3][0]); acc[3][1] = ffma2(w3, x1, acc[3][1]);
        acc[3][2] = ffma2(w3, x2, acc[3][2]); acc[3][3] = ffma2(w3, x3, acc[3][3]);
    }
#pragma unroll
    for (int a = 0; a < 4; ++a) {
        int g = g0 + gt * 4 + a;
        ull bias = dup2(brec[g]);
        ull* op = (ull*)(g_xin + (size_t)t * (HDIM * BATCH) + g * BATCH + bt * 8);
#pragma unroll
        for (int j = 0; j < 4; ++j) op[j] = fadd2(acc[a][j], bias);
    }
}

// ---------------- k_xz: xz[t,b,z] = sum_i x[b,t,i]*B_z[z,i] + b_zz[z] -------
__global__ void __launch_bounds__(64, 1) k_xz(const float* __restrict__ x,
                                              const float* __restrict__ Bz,
                                              const float* __restrict__ bzz) {
    extern __shared__ float sm[];
    float* x_s  = sm;         // [i][b]
    float* bz_s = sm + 8192;  // [i][z]
    const int tid = threadIdx.x;
    const int t   = blockIdx.x;

    for (int idx = tid; idx < 8192; idx += 64) {
        int b = idx >> 7, i = idx & 127;
        x_s[i * 64 + b] = x[(size_t)b * (T_STEPS * IDIM) + t * IDIM + i];
    }
    for (int idx = tid; idx < 4096; idx += 64) {
        int z = idx >> 7, i = idx & 127;
        bz_s[i * 32 + z] = Bz[z * IDIM + i];
    }
    __syncthreads();

    const int zt = tid >> 3;
    const int bt = tid & 7;
    float acc[4][8];
#pragma unroll
    for (int a = 0; a < 4; ++a)
#pragma unroll
        for (int j = 0; j < 8; ++j) acc[a][j] = 0.f;

    const float4* wp = (const float4*)bz_s + zt;
    const float4* xp = (const float4*)x_s + bt * 2;
#pragma unroll 4
    for (int i = 0; i < 128; ++i) {
        float4 wv = wp[i * 8];
        float4 xa = xp[i * 16];
        float4 xb = xp[i * 16 + 1];
        float xv[8] = {xa.x, xa.y, xa.z, xa.w, xb.x, xb.y, xb.z, xb.w};
#pragma unroll
        for (int j = 0; j < 8; ++j) {
            acc[0][j] = fmaf(wv.x, xv[j], acc[0][j]);
            acc[1][j] = fmaf(wv.y, xv[j], acc[1][j]);
            acc[2][j] = fmaf(wv.z, xv[j], acc[2][j]);
            acc[3][j] = fmaf(wv.w, xv[j], acc[3][j]);
        }
    }
#pragma unroll
    for (int a = 0; a < 4; ++a) {
        int z = zt * 4 + a;
        float bias = bzz[z];
#pragma unroll
        for (int j = 0; j < 8; ++j) {
            int b = bt * 8 + j;
            g_xz[(size_t)t * (BATCH * ZDIM) + b * ZDIM + z] = acc[a][j] + bias;
        }
    }
}

// ---------------- k_zscan: sequential z recursion, emits (s-0.5) ------------
__global__ void k_zscan(const float* __restrict__ Wzz,
                        const float* __restrict__ M,
                        const float* __restrict__ c,
                        float* __restrict__ dout, int out_size) {
    __shared__ float wzz_s[ZDIM * ZDIM];  // transposed [j][i]
    __shared__ float fzs[ZDIM];
    const int i = threadIdx.x;
    const int b = blockIdx.x;

    for (int idx = i; idx < ZDIM * ZDIM; idx += 32) {
        int is = idx >> 5, j = idx & 31;
        wzz_s[j * 32 + is] = Wzz[idx];
    }
    float m0 = M[i], m1 = M[ZDIM + i];
    float c0 = c[0], c1 = c[1];
    float z = 0.f;
    __syncwarp();

    for (int t = 0; t < T_STEPS; ++t) {
        fzs[i] = tanhf(z);
        __syncwarp();
        float a0 = 0.f, a1 = 0.f, a2 = 0.f, a3 = 0.f;
#pragma unroll
        for (int j = 0; j < 32; j += 4) {
            a0 = fmaf(wzz_s[(j + 0) * 32 + i], fzs[j + 0], a0);
            a1 = fmaf(wzz_s[(j + 1) * 32 + i], fzs[j + 1], a1);
            a2 = fmaf(wzz_s[(j + 2) * 32 + i], fzs[j + 2], a2);
            a3 = fmaf(wzz_s[(j + 3) * 32 + i], fzs[j + 3], a3);
        }
        float a = (a0 + a1) + (a2 + a3);
        __syncwarp();
        z = ONEMA * z + ALPHA * (a + g_xz[(size_t)t * (BATCH * ZDIM) + b * ZDIM + i]);
        float p0 = m0 * z, p1 = m1 * z;
#pragma unroll
        for (int off = 16; off; off >>= 1) {
            p0 += __shfl_xor_sync(0xffffffffu, p0, off);
            p1 += __shfl_xor_sync(0xffffffffu, p1, off);
        }
        if (i == 0) {
            size_t o = ((size_t)t * BATCH + b) * 2;
            g_sbuf[o + 0] = 1.f / (1.f + expf(-(p0 + c0))) - 0.5f;
            g_sbuf[o + 1] = 1.f / (1.f + expf(-(p1 + c1))) - 0.5f;
        }
    }
    if (out_size >= BATCH * T_STEPS + BATCH * HDIM + BATCH * ZDIM)
        dout[BATCH * T_STEPS + BATCH * HDIM + b * ZDIM + i] = z;  // zT
}

// ---------------- k_main: batch-split cluster kernel, PUSH exchange ---------
// Grid 128 = 16 clusters x 8 CTAs. Cluster cl owns batches 4cl..4cl+3; CTA
// rank p owns g rows [64p, 64p+64). Each CTA keeps a FULL local copy of the
// cluster's r state (512h x 4b = 8KB, double-buffered): after the epilogue,
// each producer thread PUSHES its r value to all 8 CTAs via st.shared::cluster
// (8KB/CTA/step written, vs 112KB/step remote reads in the pull model).
// Mainloop reads local SMEM only. One cluster.sync per step; no atomics; no
// global traffic. Clusters independent -> replay-safe, no co-residency needs.
// SMEM (floats): w_s[512][68] | v_s[512][2] | r_s[2][512][4] | part[16][768]
#define W_STRIDE 68
#define SM_V    (HDIM * W_STRIDE)          // 34816
#define SM_R    (SM_V + HDIM * 2)          // 35840
#define SM_PART (SM_R + 4096)              // 39936
#define SM_TOT  (SM_PART + 16 * 768)       // 52224 floats = 208,896 B

__global__ void __launch_bounds__(512, 1) __cluster_dims__(8, 1, 1)
k_main(const float* __restrict__ W,
       const float* __restrict__ V,
       const float* __restrict__ U,
       float* __restrict__ dout,
       int out_size) {
    extern __shared__ float sm[];
    float* w_s  = sm;
    float* v_s  = sm + SM_V;
    float* r_s  = sm + SM_R;     // [2][512h][4b]
    float* part = sm + SM_PART;
    const int tid = threadIdx.x;
    const unsigned rank = cluster_rank();
    const int g0 = (int)rank * 64;               // my g rows
    const int b0 = (blockIdx.x >> 3) * 4;        // my cluster's 4 batches

    // stage W slice [64 g][512 h] -> w_s[h][gl]
    for (int idx = tid; idx < 64 * HDIM; idx += 512) {
        int gl = idx >> 9, h = idx & 511;
        w_s[h * W_STRIDE + gl] = W[(g0 + gl) * HDIM + h];
    }
    for (int idx = tid; idx < HDIM * 2; idx += 512) v_s[idx] = V[idx];
    // zero r buffer 0 (r_0 = tanh(0) = 0) — full local copy
    for (int idx = tid; idx < 2048; idx += 512) r_s[idx] = 0.f;

    const int gl_e = tid >> 2;  // epilogue g-local (tid < 256)
    const int bl_e = tid & 3;
    float u0 = 0.f, u1 = 0.f, v = 0.f;
    if (tid < 256) {
        u0 = U[(g0 + gl_e) * 2 + 0];
        u1 = U[(g0 + gl_e) * 2 + 1];
    }
    cluster_sync();  // w_s/v_s/r_s visible; all CTAs initialized

    const int sl   = tid >> 5;   // warp = h-slice [32sl, 32sl+32)
    const int lane = tid & 31;
    const int gq   = lane >> 1;  // 16 g-quads
    const int bp   = lane & 1;   // batch pair {2bp, 2bp+1}
    const float* wbase = w_s + sl * 32 * W_STRIDE + gq * 4;
    const float* vbase = v_s + sl * 64;
    const float* rbase = r_s + sl * 128 + bp * 2;  // + buf*2048 + k*4
    const int ebase = (gl_e & 3) * 64 + (gl_e >> 2) * 4 + (bl_e >> 1) * 2 + (bl_e & 1);
    // push target byte offset builder (local address; mapa per rank)
    const unsigned r_push_base = smem_u32(r_s);

    for (int t = 0; t < T_STEPS; ++t) {
        const float* rl = rbase + (t & 1) * 2048;

        // per-step scalars (latency hidden behind mainloop)
        float xi = 0.f, s0 = 0.f, s1 = 0.f;
        if (tid < 256) {
            xi = __ldg(&g_xin[(size_t)t * (HDIM * BATCH) + (g0 + gl_e) * BATCH + b0 + bl_e]);
            const float* sp = g_sbuf + ((size_t)t * BATCH + b0 + bl_e) * 2;
            s0 = __ldg(sp); s1 = __ldg(sp + 1);
        }

        ull acc[12];
#pragma unroll
        for (int m = 0; m < 12; ++m) acc[m] = 0ULL;

#pragma unroll 4
        for (int k = 0; k < 32; ++k) {
            const float4 w4 = *(const float4*)(wbase + k * W_STRIDE);
            const float2 vv = *(const float2*)(vbase + k * 2);
            const ull r = *(const ull*)(rl + k * 4);
            const ull w0d = dup2(w4.x), w1d = dup2(w4.y);
            const ull w2d = dup2(w4.z), w3d = dup2(w4.w);
            const ull rv0 = fmul2(dup2(vv.x), r);
            const ull rv1 = fmul2(dup2(vv.y), r);
            acc[0]  = ffma2(w0d, r,   acc[0]);
            acc[1]  = ffma2(w0d, rv0, acc[1]);
            acc[2]  = ffma2(w0d, rv1, acc[2]);
            acc[3]  = ffma2(w1d, r,   acc[3]);
            acc[4]  = ffma2(w1d, rv0, acc[4]);
            acc[5]  = ffma2(w1d, rv1, acc[5]);
            acc[6]  = ffma2(w2d, r,   acc[6]);
            acc[7]  = ffma2(w2d, rv0, acc[7]);
            acc[8]  = ffma2(w2d, rv1, acc[8]);
            acc[9]  = ffma2(w3d, r,   acc[9]);
            acc[10] = ffma2(w3d, rv0, acc[10]);
            acc[11] = ffma2(w3d, rv1, acc[11]);
        }

        // partials: word = sl*768 + (m*4 + a)*64 + gq*4 + bp*2
        {
            float* pb = part + sl * 768 + gq * 4 + bp * 2;
#pragma unroll
            for (int m = 0; m < 3; ++m)
#pragma unroll
                for (int a = 0; a < 4; ++a)
                    *(ull*)(pb + (m * 4 + a) * 64) = acc[a * 3 + m];
        }
        __syncthreads();

        // epilogue: threads 0..255 own (g = g0+gl_e, b = b0+bl_e)
        if (tid < 256) {
            float y0 = 0.f, y1 = 0.f, y2 = 0.f;
            const float* q = part + ebase;
#pragma unroll
            for (int s = 0; s < 16; ++s) {
                y0 += q[s * 768];
                y1 += q[s * 768 + 256];
                y2 += q[s * 768 + 512];
            }
            v = ONEMA * v + ALPHA * (y0 + s0 * u0 * y1 + s1 * u1 * y2 + xi);
            const float r = tanhf(v);
            // push r to the (t+1)-parity tile of ALL 8 CTAs (incl. self)
            const unsigned dst = r_push_base +
                (unsigned)((((t + 1) & 1) * 2048 + (g0 + gl_e) * 4 + bl_e) * 4);
#pragma unroll
            for (unsigned p = 0; p < 8; ++p) stsc32(mapa_u32(dst, p), r);
            // trace for k_out (coalesced within quad; fire-and-forget)
            g_rbuf[(size_t)(t + 1) * (HDIM * BATCH) + (g0 + gl_e) * BATCH + b0 + bl_e] = r;
            if (t == T_STEPS - 1 && out_size >= BATCH * T_STEPS + BATCH * HDIM)
                dout[BATCH * T_STEPS + (b0 + bl_e) * HDIM + g0 + gl_e] = v;  // vT
        }
        cluster_sync();  // pushes visible cluster-wide (arrive = release)
    }
}

// ---------------- k_out: y[b,t] = tanh(v_{t+1}) @ w_out + b_out -------------
__global__ void __launch_bounds__(256, 1) k_out(const float* __restrict__ wout,
                                                const float* __restrict__ bout,
                                                float* __restrict__ dout,
                                                int out_size) {
    __shared__ float w_sh[HDIM];
    const int tid = threadIdx.x;
    w_sh[tid] = wout[tid];
    w_sh[tid + 256] = wout[tid + 256];
    __syncthreads();
    int gid = blockIdx.x * 256 + tid;
    int b = gid & 63, t = gid >> 6;
    const float* rp = g_rbuf + (size_t)(t + 1) * (HDIM * BATCH) + b;
    float acc = bout[0];
#pragma unroll 8
    for (int g = 0; g < HDIM; ++g) acc = fmaf(rp[g * BATCH], w_sh[g], acc);
    int o = b * T_STEPS + t;
    if (o < out_size) dout[o] = acc;
}

// ---------------- launch -----------------------------------------------------
extern "C" void kernel_launch(void* const* d_in, const int* in_sizes, int n_in,
                              void* d_out, int out_size) {
    const float* x    = (const float*)d_in[0];
    const float* win  = (const float*)d_in[1];
    const float* wrec = (const float*)d_in[2];
    const float* brec = (const float*)d_in[3];
    const float* wout = (const float*)d_in[4];
    const float* bout = (const float*)d_in[5];
    const float* wzz  = (const float*)d_in[6];
    const float* bzz  = (const float*)d_in[7];
    const float* Bz   = (const float*)d_in[8];
    const float* M    = (const float*)d_in[9];
    const float* c    = (const float*)d_in[10];
    const float* U    = (const float*)d_in[11];
    const float* V    = (const float*)d_in[12];
    float* out = (float*)d_out;

    cudaFuncSetAttribute(k_xin,  cudaFuncAttributeMaxDynamicSharedMemorySize, 16384 * 4);
    cudaFuncSetAttribute(k_xz,   cudaFuncAttributeMaxDynamicSharedMemorySize, 12288 * 4);
    cudaFuncSetAttribute(k_main, cudaFuncAttributeMaxDynamicSharedMemorySize, SM_TOT * 4);

    k_xz<<<T_STEPS, 64, 12288 * 4>>>(x, Bz, bzz);
    k_zscan<<<BATCH, 32>>>(wzz, M, c, out, out_size);
    k_xin<<<dim3(T_STEPS, HDIM / 64), 128, 16384 * 4>>>(x, win, brec);
    k_main<<<128, 512, SM_TOT * 4>>>(wrec, V, U, out, out_size);
    k_out<<<(BATCH * T_STEPS) / 256, 256>>>(wout, bout, out, out_size);
}

// round 14
// speedup vs baseline: 1.0017x; 1.0017x over previous
#include <cuda_runtime.h>

#define T_STEPS 512
#define BATCH   64
#define IDIM    128
#define HDIM    512
#define ZDIM    32
#define ALPHA 0.2f
#define ONEMA 0.8f

typedef unsigned long long ull;

// ---------------- device scratch (static globals; no runtime allocation) ----
__device__ float g_xin [(size_t)T_STEPS * HDIM * BATCH];        // (t, g, b)
__device__ float g_rbuf[(size_t)(T_STEPS + 1) * HDIM * BATCH];  // (t, h, b)
__device__ float g_xz  [(size_t)T_STEPS * BATCH * ZDIM];        // (t, b, z)
__device__ float g_sbuf[(size_t)T_STEPS * BATCH * 2];           // (t, b, k): s-0.5

// ---------------- helpers ---------------------------------------------------
__device__ __forceinline__ unsigned smem_u32(const void* p) {
    return (unsigned)__cvta_generic_to_shared(p);
}
// packed fp32x2 math (sm_100+)
__device__ __forceinline__ ull ffma2(ull a, ull b, ull c) {
    ull d; asm("fma.rn.f32x2 %0,%1,%2,%3;" : "=l"(d) : "l"(a), "l"(b), "l"(c)); return d;
}
__device__ __forceinline__ ull fmul2(ull a, ull b) {
    ull d; asm("mul.rn.f32x2 %0,%1,%2;" : "=l"(d) : "l"(a), "l"(b)); return d;
}
__device__ __forceinline__ ull fadd2(ull a, ull b) {
    ull d; asm("add.rn.f32x2 %0,%1,%2;" : "=l"(d) : "l"(a), "l"(b)); return d;
}
__device__ __forceinline__ ull dup2(float x) {
    ull d; asm("mov.b64 %0,{%1,%1};" : "=l"(d) : "f"(x)); return d;
}
// distributed shared memory
__device__ __forceinline__ unsigned cluster_rank() {
    unsigned r; asm("mov.u32 %0, %%cluster_ctarank;" : "=r"(r)); return r;
}
__device__ __forceinline__ unsigned mapa_u32(unsigned local_addr, unsigned rank) {
    unsigned r;
    asm("mapa.shared::cluster.u32 %0, %1, %2;" : "=r"(r) : "r"(local_addr), "r"(rank));
    return r;
}
__device__ __forceinline__ void stsc32(unsigned a, float v) {
    asm volatile("st.shared::cluster.f32 [%0], %1;" :: "r"(a), "f"(v) : "memory");
}
__device__ __forceinline__ void cluster_sync() {
    asm volatile("barrier.cluster.arrive.aligned;" ::: "memory");
    asm volatile("barrier.cluster.wait.aligned;" ::: "memory");
}

// ---------------- k_xin: xin[t,g,b] = sum_i x[b,t,i]*W_in[g,i] + b_rec[g] ----
__global__ void __launch_bounds__(128, 1) k_xin(const float* __restrict__ x,
                                                const float* __restrict__ win,
                                                const float* __restrict__ brec) {
    extern __shared__ float sm[];
    float* x_s = sm;         // [i][b]
    float* w_s = sm + 8192;  // [i][gl]
    const int tid = threadIdx.x;
    const int t   = blockIdx.x;
    const int g0  = blockIdx.y * 64;

    for (int idx = tid; idx < 8192; idx += 128) {
        int b = idx >> 7, i = idx & 127;
        x_s[i * 64 + b] = x[(size_t)b * (T_STEPS * IDIM) + t * IDIM + i];
    }
    for (int idx = tid; idx < 8192; idx += 128) {
        int gl = idx >> 7, i = idx & 127;
        w_s[i * 64 + gl] = win[(g0 + gl) * IDIM + i];
    }
    __syncthreads();

    const int gt = tid >> 3;
    const int bt = tid & 7;
    ull acc[4][4];
#pragma unroll
    for (int a = 0; a < 4; ++a)
#pragma unroll
        for (int j = 0; j < 4; ++j) acc[a][j] = 0ULL;

    const float4* wp = (const float4*)w_s + gt;
    const ull* xp = (const ull*)x_s + bt * 4;
#pragma unroll 4
    for (int i = 0; i < 128; ++i) {
        float4 wv = wp[i * 16];
        ull x0 = xp[i * 32], x1 = xp[i * 32 + 1], x2 = xp[i * 32 + 2], x3 = xp[i * 32 + 3];
        ull w0 = dup2(wv.x), w1 = dup2(wv.y), w2 = dup2(wv.z), w3 = dup2(wv.w);
        acc[0][0] = ffma2(w0, x0, acc[0][0]); acc[0][1] = ffma2(w0, x1, acc[0][1]);
        acc[0][2] = ffma2(w0, x2, acc[0][2]); acc[0][3] = ffma2(w0, x3, acc[0][3]);
        acc[1][0] = ffma2(w1, x0, acc[1][0]); acc[1][1] = ffma2(w1, x1, acc[1][1]);
        acc[1][2] = ffma2(w1, x2, acc[1][2]); acc[1][3] = ffma2(w1, x3, acc[1][3]);
        acc[2][0] = ffma2(w2, x0, acc[2][0]); acc[2][1] = ffma2(w2, x1, acc[2][1]);
        acc[2][2] = ffma2(w2, x2, acc[2][2]); acc[2][3] = ffma2(w2, x3, acc[2][3]);
        acc[3][0] = ffma2(w3, x0, acc[3][0]); acc[3][1] = ffma2(w3, x1, acc[3][1]);
        acc[3][2] = ffma2(w3, x2, acc[3][2]); acc[3][3] = ffma2(w3, x3, acc[3][3]);
    }
#pragma unroll
    for (int a = 0; a < 4; ++a) {
        int g = g0 + gt * 4 + a;
        ull bias = dup2(brec[g]);
        ull* op = (ull*)(g_xin + (size_t)t * (HDIM * BATCH) + g * BATCH + bt * 8);
#pragma unroll
        for (int j = 0; j < 4; ++j) op[j] = fadd2(acc[a][j], bias);
    }
}

// ---------------- k_xz: xz[t,b,z] = sum_i x[b,t,i]*B_z[z,i] + b_zz[z] -------
__global__ void __launch_bounds__(64, 1) k_xz(const float* __restrict__ x,
                                              const float* __restrict__ Bz,
                                              const float* __restrict__ bzz) {
    extern __shared__ float sm[];
    float* x_s  = sm;         // [i][b]
    float* bz_s = sm + 8192;  // [i][z]
    const int tid = threadIdx.x;
    const int t   = blockIdx.x;

    for (int idx = tid; idx < 8192; idx += 64) {
        int b = idx >> 7, i = idx & 127;
        x_s[i * 64 + b] = x[(size_t)b * (T_STEPS * IDIM) + t * IDIM + i];
    }
    for (int idx = tid; idx < 4096; idx += 64) {
        int z = idx >> 7, i = idx & 127;
        bz_s[i * 32 + z] = Bz[z * IDIM + i];
    }
    __syncthreads();

    const int zt = tid >> 3;
    const int bt = tid & 7;
    float acc[4][8];
#pragma unroll
    for (int a = 0; a < 4; ++a)
#pragma unroll
        for (int j = 0; j < 8; ++j) acc[a][j] = 0.f;

    const float4* wp = (const float4*)bz_s + zt;
    const float4* xp = (const float4*)x_s + bt * 2;
#pragma unroll 4
    for (int i = 0; i < 128; ++i) {
        float4 wv = wp[i * 8];
        float4 xa = xp[i * 16];
        float4 xb = xp[i * 16 + 1];
        float xv[8] = {xa.x, xa.y, xa.z, xa.w, xb.x, xb.y, xb.z, xb.w};
#pragma unroll
        for (int j = 0; j < 8; ++j) {
            acc[0][j] = fmaf(wv.x, xv[j], acc[0][j]);
            acc[1][j] = fmaf(wv.y, xv[j], acc[1][j]);
            acc[2][j] = fmaf(wv.z, xv[j], acc[2][j]);
            acc[3][j] = fmaf(wv.w, xv[j], acc[3][j]);
        }
    }
#pragma unroll
    for (int a = 0; a < 4; ++a) {
        int z = zt * 4 + a;
        float bias = bzz[z];
#pragma unroll
        for (int j = 0; j < 8; ++j) {
            int b = bt * 8 + j;
            g_xz[(size_t)t * (BATCH * ZDIM) + b * ZDIM + z] = acc[a][j] + bias;
        }
    }
}

// ---------------- k_zscan: sequential z recursion, emits (s-0.5) ------------
__global__ void k_zscan(const float* __restrict__ Wzz,
                        const float* __restrict__ M,
                        const float* __restrict__ c,
                        float* __restrict__ dout, int out_size) {
    __shared__ float wzz_s[ZDIM * ZDIM];  // transposed [j][i]
    __shared__ float fzs[ZDIM];
    const int i = threadIdx.x;
    const int b = blockIdx.x;

    for (int idx = i; idx < ZDIM * ZDIM; idx += 32) {
        int is = idx >> 5, j = idx & 31;
        wzz_s[j * 32 + is] = Wzz[idx];
    }
    float m0 = M[i], m1 = M[ZDIM + i];
    float c0 = c[0], c1 = c[1];
    float z = 0.f;
    __syncwarp();

    for (int t = 0; t < T_STEPS; ++t) {
        fzs[i] = tanhf(z);
        __syncwarp();
        float a0 = 0.f, a1 = 0.f, a2 = 0.f, a3 = 0.f;
#pragma unroll
        for (int j = 0; j < 32; j += 4) {
            a0 = fmaf(wzz_s[(j + 0) * 32 + i], fzs[j + 0], a0);
            a1 = fmaf(wzz_s[(j + 1) * 32 + i], fzs[j + 1], a1);
            a2 = fmaf(wzz_s[(j + 2) * 32 + i], fzs[j + 2], a2);
            a3 = fmaf(wzz_s[(j + 3) * 32 + i], fzs[j + 3], a3);
        }
        float a = (a0 + a1) + (a2 + a3);
        __syncwarp();
        z = ONEMA * z + ALPHA * (a + g_xz[(size_t)t * (BATCH * ZDIM) + b * ZDIM + i]);
        float p0 = m0 * z, p1 = m1 * z;
#pragma unroll
        for (int off = 16; off; off >>= 1) {
            p0 += __shfl_xor_sync(0xffffffffu, p0, off);
            p1 += __shfl_xor_sync(0xffffffffu, p1, off);
        }
        if (i == 0) {
            size_t o = ((size_t)t * BATCH + b) * 2;
            g_sbuf[o + 0] = 1.f / (1.f + expf(-(p0 + c0))) - 0.5f;
            g_sbuf[o + 1] = 1.f / (1.f + expf(-(p1 + c1))) - 0.5f;
        }
    }
    if (out_size >= BATCH * T_STEPS + BATCH * HDIM + BATCH * ZDIM)
        dout[BATCH * T_STEPS + BATCH * HDIM + b * ZDIM + i] = z;  // zT
}

// ---------------- k_main: batch-split cluster kernel, PUSH exchange ---------
// Grid 128 = 16 clusters x 8 CTAs. Cluster cl owns batches 4cl..4cl+3; CTA
// rank p owns g rows [64p, 64p+64). Each CTA keeps a FULL local copy of the
// cluster's r state (512h x 4b = 8KB, double-buffered): after the epilogue,
// each producer thread PUSHES its r value to all 8 CTAs via st.shared::cluster
// (8KB/CTA/step written, vs 112KB/step remote reads in the pull model).
// Mainloop reads local SMEM only. One cluster.sync per step; no atomics; no
// global traffic. Clusters independent -> replay-safe, no co-residency needs.
// SMEM (floats): w_s[512][68] | v_s[512][2] | r_s[2][512][4] | part[16][768]
#define W_STRIDE 68
#define SM_V    (HDIM * W_STRIDE)          // 34816
#define SM_R    (SM_V + HDIM * 2)          // 35840
#define SM_PART (SM_R + 4096)              // 39936
#define SM_TOT  (SM_PART + 16 * 768)       // 52224 floats = 208,896 B

__global__ void __launch_bounds__(512, 1) __cluster_dims__(8, 1, 1)
k_main(const float* __restrict__ W,
       const float* __restrict__ V,
       const float* __restrict__ U,
       float* __restrict__ dout,
       int out_size) {
    extern __shared__ float sm[];
    float* w_s  = sm;
    float* v_s  = sm + SM_V;
    float* r_s  = sm + SM_R;     // [2][512h][4b]
    float* part = sm + SM_PART;
    const int tid = threadIdx.x;
    const unsigned rank = cluster_rank();
    const int g0 = (int)rank * 64;               // my g rows
    const int b0 = (blockIdx.x >> 3) * 4;        // my cluster's 4 batches

    // stage W slice [64 g][512 h] -> w_s[h][gl]
    for (int idx = tid; idx < 64 * HDIM; idx += 512) {
        int gl = idx >> 9, h = idx & 511;
        w_s[h * W_STRIDE + gl] = W[(g0 + gl) * HDIM + h];
    }
    for (int idx = tid; idx < HDIM * 2; idx += 512) v_s[idx] = V[idx];
    // zero r buffer 0 (r_0 = tanh(0) = 0) — full local copy
    for (int idx = tid; idx < 2048; idx += 512) r_s[idx] = 0.f;

    const int gl_e = tid >> 2;  // epilogue g-local (tid < 256)
    const int bl_e = tid & 3;
    float u0 = 0.f, u1 = 0.f, v = 0.f;
    if (tid < 256) {
        u0 = U[(g0 + gl_e) * 2 + 0];
        u1 = U[(g0 + gl_e) * 2 + 1];
    }
    cluster_sync();  // w_s/v_s/r_s visible; all CTAs initialized

    const int sl   = tid >> 5;   // warp = h-slice [32sl, 32sl+32)
    const int lane = tid & 31;
    const int gq   = lane >> 1;  // 16 g-quads
    const int bp   = lane & 1;   // batch pair {2bp, 2bp+1}
    const float* wbase = w_s + sl * 32 * W_STRIDE + gq * 4;
    const float* vbase = v_s + sl * 64;
    const float* rbase = r_s + sl * 128 + bp * 2;  // + buf*2048 + k*4
    const int ebase = (gl_e & 3) * 64 + (gl_e >> 2) * 4 + (bl_e >> 1) * 2 + (bl_e & 1);
    // push target byte offset builder (local address; mapa per rank)
    const unsigned r_push_base = smem_u32(r_s);

    for (int t = 0; t < T_STEPS; ++t) {
        const float* rl = rbase + (t & 1) * 2048;

        // per-step scalars (latency hidden behind mainloop)
        float xi = 0.f, s0 = 0.f, s1 = 0.f;
        if (tid < 256) {
            xi = __ldg(&g_xin[(size_t)t * (HDIM * BATCH) + (g0 + gl_e) * BATCH + b0 + bl_e]);
            const float* sp = g_sbuf + ((size_t)t * BATCH + b0 + bl_e) * 2;
            s0 = __ldg(sp); s1 = __ldg(sp + 1);
        }

        ull acc[12];
#pragma unroll
        for (int m = 0; m < 12; ++m) acc[m] = 0ULL;

#pragma unroll 4
        for (int k = 0; k < 32; ++k) {
            const float4 w4 = *(const float4*)(wbase + k * W_STRIDE);
            const float2 vv = *(const float2*)(vbase + k * 2);
            const ull r = *(const ull*)(rl + k * 4);
            const ull w0d = dup2(w4.x), w1d = dup2(w4.y);
            const ull w2d = dup2(w4.z), w3d = dup2(w4.w);
            const ull rv0 = fmul2(dup2(vv.x), r);
            const ull rv1 = fmul2(dup2(vv.y), r);
            acc[0]  = ffma2(w0d, r,   acc[0]);
            acc[1]  = ffma2(w0d, rv0, acc[1]);
            acc[2]  = ffma2(w0d, rv1, acc[2]);
            acc[3]  = ffma2(w1d, r,   acc[3]);
            acc[4]  = ffma2(w1d, rv0, acc[4]);
            acc[5]  = ffma2(w1d, rv1, acc[5]);
            acc[6]  = ffma2(w2d, r,   acc[6]);
            acc[7]  = ffma2(w2d, rv0, acc[7]);
            acc[8]  = ffma2(w2d, rv1, acc[8]);
            acc[9]  = ffma2(w3d, r,   acc[9]);
            acc[10] = ffma2(w3d, rv0, acc[10]);
            acc[11] = ffma2(w3d, rv1, acc[11]);
        }

        // partials: word = sl*768 + (m*4 + a)*64 + gq*4 + bp*2
        {
            float* pb = part + sl * 768 + gq * 4 + bp * 2;
#pragma unroll
            for (int m = 0; m < 3; ++m)
#pragma unroll
                for (int a = 0; a < 4; ++a)
                    *(ull*)(pb + (m * 4 + a) * 64) = acc[a * 3 + m];
        }
        __syncthreads();

        // epilogue: threads 0..255 own (g = g0+gl_e, b = b0+bl_e)
        if (tid < 256) {
            float y0 = 0.f, y1 = 0.f, y2 = 0.f;
            const float* q = part + ebase;
#pragma unroll
            for (int s = 0; s < 16; ++s) {
                y0 += q[s * 768];
                y1 += q[s * 768 + 256];
                y2 += q[s * 768 + 512];
            }
            v = ONEMA * v + ALPHA * (y0 + s0 * u0 * y1 + s1 * u1 * y2 + xi);
            const float r = tanhf(v);
            // push r to the (t+1)-parity tile of ALL 8 CTAs (incl. self)
            const unsigned dst = r_push_base +
                (unsigned)((((t + 1) & 1) * 2048 + (g0 + gl_e) * 4 + bl_e) * 4);
#pragma unroll
            for (unsigned p = 0; p < 8; ++p) stsc32(mapa_u32(dst, p), r);
            // trace for k_out (coalesced within quad; fire-and-forget)
            g_rbuf[(size_t)(t + 1) * (HDIM * BATCH) + (g0 + gl_e) * BATCH + b0 + bl_e] = r;
            if (t == T_STEPS - 1 && out_size >= BATCH * T_STEPS + BATCH * HDIM)
                dout[BATCH * T_STEPS + (b0 + bl_e) * HDIM + g0 + gl_e] = v;  // vT
        }
        cluster_sync();  // pushes visible cluster-wide (arrive = release)
    }
}

// ---------------- k_out: y[b,t] = tanh(v_{t+1}) @ w_out + b_out -------------
__global__ void __launch_bounds__(256, 1) k_out(const float* __restrict__ wout,
                                                const float* __restrict__ bout,
                                                float* __restrict__ dout,
                                                int out_size) {
    __shared__ float w_sh[HDIM];
    const int tid = threadIdx.x;
    w_sh[tid] = wout[tid];
    w_sh[tid + 256] = wout[tid + 256];
    __syncthreads();
    int gid = blockIdx.x * 256 + tid;
    int b = gid & 63, t = gid >> 6;
    const float* rp = g_rbuf + (size_t)(t + 1) * (HDIM * BATCH) + b;
    float acc = bout[0];
#pragma unroll 8
    for (int g = 0; g < HDIM; ++g) acc = fmaf(rp[g * BATCH], w_sh[g], acc);
    int o = b * T_STEPS + t;
    if (o < out_size) dout[o] = acc;
}

// ---------------- launch -----------------------------------------------------
extern "C" void kernel_launch(void* const* d_in, const int* in_sizes, int n_in,
                              void* d_out, int out_size) {
    const float* x    = (const float*)d_in[0];
    const float* win  = (const float*)d_in[1];
    const float* wrec = (const float*)d_in[2];
    const float* brec = (const float*)d_in[3];
    const float* wout = (const float*)d_in[4];
    const float* bout = (const float*)d_in[5];
    const float* wzz  = (const float*)d_in[6];
    const float* bzz  = (const float*)d_in[7];
    const float* Bz   = (const float*)d_in[8];
    const float* M    = (const float*)d_in[9];
    const float* c    = (const float*)d_in[10];
    const float* U    = (const float*)d_in[11];
    const float* V    = (const float*)d_in[12];
    float* out = (float*)d_out;

    cudaFuncSetAttribute(k_xin,  cudaFuncAttributeMaxDynamicSharedMemorySize, 16384 * 4);
    cudaFuncSetAttribute(k_xz,   cudaFuncAttributeMaxDynamicSharedMemorySize, 12288 * 4);
    cudaFuncSetAttribute(k_main, cudaFuncAttributeMaxDynamicSharedMemorySize, SM_TOT * 4);

    k_xz<<<T_STEPS, 64, 12288 * 4>>>(x, Bz, bzz);
    k_zscan<<<BATCH, 32>>>(wzz, M, c, out, out_size);
    k_xin<<<dim3(T_STEPS, HDIM / 64), 128, 16384 * 4>>>(x, win, brec);
    k_main<<<128, 512, SM_TOT * 4>>>(wrec, V, U, out, out_size);
    k_out<<<(BATCH * T_STEPS) / 256, 256>>>(wout, bout, out, out_size);
}